// round 16
// baseline (speedup 1.0000x reference)
#include <cuda_runtime.h>
#include <cstdint>

// Problem constants
#define BB 4
#define NN 16384
#define DD 128
#define PP 100
#define BN (BB * NN)          // 65536 points
#define PPAD 128              // padded projection count
#define NSEG (PP * BB)        // 400 independent segments
#define NITEMS (PP * BN)      // 6,553,600

// ---------------- device scratch (no allocations allowed) ----------------
__device__ float g_xp[NITEMS];       // x projections, [p][b][n] (segment-contiguous)
__device__ float g_yp[NITEMS];       // y projections
__device__ float g_delta[NITEMS];    // transported_proj - x_proj
__device__ float g_thn[PP * DD];     // normalized thetas, [p][d]
__device__ float g_thn_t[DD * PPAD]; // normalized thetas transposed, [d][p] (padded)

// ---------------- K1: normalize thetas ----------------
__global__ void __launch_bounds__(128) norm_kernel(const float* __restrict__ thetas) {
    int p = blockIdx.x;   // 0..127
    int d = threadIdx.x;  // 0..127
    __shared__ float red[4];
    float v = (p < PP) ? thetas[p * DD + d] : 0.f;
    float ss = v * v;
    #pragma unroll
    for (int o = 16; o; o >>= 1) ss += __shfl_xor_sync(0xFFFFFFFFu, ss, o);
    if ((d & 31) == 0) red[d >> 5] = ss;
    __syncthreads();
    float tot = red[0] + red[1] + red[2] + red[3];
    float w = 0.f;
    if (p < PP) {
        w = v / fmaxf(sqrtf(tot), 1e-12f);
        g_thn[p * DD + d] = w;
    }
    g_thn_t[d * PPAD + p] = w;  // zero for padded p
}

// ---------------- K2: projections (fp32 GEMM, 8x8 per thread) ----------------
#define XT_PITCH 136
#define PROJ_SMEM ((DD * PPAD + DD * XT_PITCH) * 4)

__global__ void __launch_bounds__(256) proj_kernel(const float* __restrict__ x,
                                                   const float* __restrict__ y) {
    extern __shared__ float psm[];
    float* th_s = psm;                 // [d * 128 + p]
    float* xt_s = psm + DD * PPAD;     // [d * 136 + r]
    int tid = threadIdx.x;
    int bn0 = blockIdx.x * 128;

    #pragma unroll
    for (int i = tid; i < DD * PPAD; i += 256) th_s[i] = g_thn_t[i];

    const float* srcs[2] = {x, y};
    float* dsts[2] = {g_xp, g_yp};
    int tx = tid & 15;   // bn lane
    int ty = tid >> 4;   // p group

    for (int a = 0; a < 2; a++) {
        const float* src = srcs[a];
        __syncthreads();
        for (int e = tid; e < DD * 128; e += 256) {
            int r = e >> 7, d = e & 127;
            xt_s[d * XT_PITCH + r] = src[(size_t)(bn0 + r) * DD + d];
        }
        __syncthreads();

        float acc[8][8];
        #pragma unroll
        for (int i = 0; i < 8; i++)
            #pragma unroll
            for (int j = 0; j < 8; j++) acc[i][j] = 0.f;

        #pragma unroll 4
        for (int d = 0; d < DD; d++) {
            float4 a0 = *(const float4*)&th_s[d * PPAD + ty * 8];
            float4 a1 = *(const float4*)&th_s[d * PPAD + ty * 8 + 4];
            float av[8] = {a0.x, a0.y, a0.z, a0.w, a1.x, a1.y, a1.z, a1.w};
            float bv[8];
            #pragma unroll
            for (int j = 0; j < 8; j++) bv[j] = xt_s[d * XT_PITCH + tx + 16 * j];
            #pragma unroll
            for (int pi = 0; pi < 8; pi++)
                #pragma unroll
                for (int j = 0; j < 8; j++) acc[pi][j] = fmaf(av[pi], bv[j], acc[pi][j]);
        }

        float* dst = dsts[a];
        #pragma unroll
        for (int pi = 0; pi < 8; pi++) {
            int p = ty * 8 + pi;
            if (p < PP) {
                #pragma unroll
                for (int j = 0; j < 8; j++)
                    dst[(size_t)p * BN + bn0 + tx + 16 * j] = acc[pi][j];
            }
        }
    }
}

// ---------------- K3: counting-rank transport, ONE atomic per element ----------------
// One block per segment. 16384 linear bins over [-6,6] (width 7.3e-4); within-bin
// rank order arbitrary -> ranks remain an exact permutation, value mismatch
// bounded by one bin width (output error ~6e-6, tolerance 1e-3).
// Key change vs R15: the histogram atomicAdd's RETURN VALUE is the within-bin
// arrival index. Stash (bin<<18)|arrival in shared; after the exclusive scan,
// rank = hist[bin] + arrival -- the scatter pass needs NO atomics. Atomic lane
// count (the ATOMS 2cyc/lane bottleneck) is halved.
#define ST 512
#define NBIN 16384
#define BINS_PER_WARP (NBIN / 16)          // 1024
#define SCAN_ROUNDS (BINS_PER_WARP / 32)   // 32
// dynamic smem: hist 64KB + ys 64KB + saux 64KB = 192KB
#define SD_SMEM (NBIN * 4 + NN * 4 + NN * 4)

__device__ __forceinline__ int binof(float v) {
    // monotone: fp add/mul by positive const + truncation preserve order
    int b = (int)((v + 6.0f) * (float)(NBIN / 12.0));
    return min(max(b, 0), NBIN - 1);
}

__global__ void __launch_bounds__(ST, 1) sortdelta_kernel() {
    extern __shared__ char sdm[];
    int* hist = (int*)sdm;
    float* ys = (float*)(sdm + NBIN * 4);
    unsigned* saux = (unsigned*)(sdm + NBIN * 4 + NN * 4);
    __shared__ int wsum[16];

    int seg = blockIdx.x;
    size_t base = (size_t)seg * NN;
    int t = threadIdx.x, lane = t & 31, warp = t >> 5;

    #pragma unroll 1
    for (int phase = 0; phase < 2; phase++) {
        const float* src = phase == 0 ? (g_yp + base) : (g_xp + base);

        // ---- zero + histogram; record per-element (bin, arrival) ----
        for (int i = t; i < NBIN; i += ST) hist[i] = 0;
        __syncthreads();
        #pragma unroll 4
        for (int i = t; i < NN; i += ST) {
            int b = binof(src[i]);
            unsigned a = (unsigned)atomicAdd(&hist[b], 1);
            saux[i] = ((unsigned)b << 18) | a;   // bin:14b | arrival:18b
        }
        __syncthreads();

        // ---- exclusive scan of NBIN counts (warp-strided, conflict-free) ----
        {
            int wbase = warp * BINS_PER_WARP;
            int carry = 0;
            #pragma unroll 4
            for (int r = 0; r < SCAN_ROUNDS; r++) {
                int idx = wbase + r * 32 + lane;
                int c = hist[idx];
                int inc = c;
                #pragma unroll
                for (int o = 1; o < 32; o <<= 1) {
                    int n = __shfl_up_sync(0xFFFFFFFFu, inc, o);
                    if (lane >= o) inc += n;
                }
                hist[idx] = carry + inc - c;  // exclusive
                carry += __shfl_sync(0xFFFFFFFFu, inc, 31);
            }
            if (lane == 0) wsum[warp] = carry;
        }
        __syncthreads();
        if (warp == 0) {
            int w = (lane < 16) ? wsum[lane] : 0;
            #pragma unroll
            for (int o = 1; o < 16; o <<= 1) {
                int n = __shfl_up_sync(0xFFFFFFFFu, w, o);
                if (lane >= o) w += n;
            }
            if (lane < 16) wsum[lane] = w;  // inclusive
        }
        __syncthreads();
        if (warp > 0) {
            int off = wsum[warp - 1];
            int wbase = warp * BINS_PER_WARP;
            #pragma unroll 4
            for (int r = 0; r < SCAN_ROUNDS; r++)
                hist[wbase + r * 32 + lane] += off;
        }
        __syncthreads();

        // ---- scatter, atomic-free: rank = bin base + arrival ----
        if (phase == 0) {
            #pragma unroll 4
            for (int i = t; i < NN; i += ST) {
                unsigned u = saux[i];
                int r = hist[u >> 18] + (int)(u & 0x3FFFFu);
                ys[r] = src[i];
            }
        } else {
            #pragma unroll 4
            for (int i = t; i < NN; i += ST) {
                unsigned u = saux[i];
                int r = hist[u >> 18] + (int)(u & 0x3FFFFu);
                g_delta[base + i] = ys[r] - src[i];
            }
        }
        __syncthreads();  // ys complete / hist+saux reuse
    }
}

// ---------------- K4: out = x + (Delta^T @ Thn)/P ----------------
#define OUT_SMEM (2 * PP * DD * 4)

__global__ void __launch_bounds__(256) out_kernel(const float* __restrict__ x,
                                                  float* __restrict__ out) {
    extern __shared__ float osm[];
    float* dl_s = osm;             // [p][bn_local] 100x128
    float* th_s = osm + PP * DD;   // [p][d]        100x128
    int tid = threadIdx.x;
    int bn0 = blockIdx.x * 128;

    for (int e = tid; e < PP * DD; e += 256) {
        th_s[e] = g_thn[e];
        int p = e >> 7, j = e & 127;
        dl_s[e] = g_delta[(size_t)p * BN + bn0 + j];
    }
    __syncthreads();

    int tx = tid & 15;  // d lane: d = tx + 16*k
    int ty = tid >> 4;  // bn group: bn = bn0 + ty*8 + bi

    float acc[8][8];
    #pragma unroll
    for (int i = 0; i < 8; i++)
        #pragma unroll
        for (int j = 0; j < 8; j++) acc[i][j] = 0.f;

    #pragma unroll 4
    for (int p = 0; p < PP; p++) {
        float4 a0 = *(const float4*)&dl_s[p * DD + ty * 8];
        float4 a1 = *(const float4*)&dl_s[p * DD + ty * 8 + 4];
        float av[8] = {a0.x, a0.y, a0.z, a0.w, a1.x, a1.y, a1.z, a1.w};
        float bv[8];
        #pragma unroll
        for (int k = 0; k < 8; k++) bv[k] = th_s[p * DD + tx + 16 * k];
        #pragma unroll
        for (int bi = 0; bi < 8; bi++)
            #pragma unroll
            for (int k = 0; k < 8; k++) acc[bi][k] = fmaf(av[bi], bv[k], acc[bi][k]);
    }

    const float s = 1.0f / (float)PP;
    #pragma unroll
    for (int bi = 0; bi < 8; bi++) {
        size_t row = (size_t)(bn0 + ty * 8 + bi) * DD;
        #pragma unroll
        for (int k = 0; k < 8; k++) {
            size_t o = row + tx + 16 * k;
            out[o] = x[o] + s * acc[bi][k];
        }
    }
}

// ---------------- launch ----------------
extern "C" void kernel_launch(void* const* d_in, const int* in_sizes, int n_in,
                              void* d_out, int out_size) {
    const float* x = (const float*)d_in[0];
    const float* y = (const float*)d_in[1];
    const float* th = (const float*)d_in[2];
    float* out = (float*)d_out;
    (void)in_sizes; (void)n_in; (void)out_size;

    cudaFuncSetAttribute(proj_kernel,      cudaFuncAttributeMaxDynamicSharedMemorySize, PROJ_SMEM);
    cudaFuncSetAttribute(sortdelta_kernel, cudaFuncAttributeMaxDynamicSharedMemorySize, SD_SMEM);
    cudaFuncSetAttribute(out_kernel,       cudaFuncAttributeMaxDynamicSharedMemorySize, OUT_SMEM);

    norm_kernel<<<128, 128>>>(th);
    proj_kernel<<<512, 256, PROJ_SMEM>>>(x, y);
    sortdelta_kernel<<<NSEG, ST, SD_SMEM>>>();
    out_kernel<<<512, 256, OUT_SMEM>>>(x, out);
}

// round 17
// speedup vs baseline: 1.9711x; 1.9711x over previous
#include <cuda_runtime.h>
#include <cstdint>

// Problem constants
#define BB 4
#define NN 16384
#define DD 128
#define PP 100
#define BN (BB * NN)          // 65536 points
#define PPAD 128              // padded projection count
#define NSEG (PP * BB)        // 400 independent segments
#define NITEMS (PP * BN)      // 6,553,600

// ---------------- device scratch (no allocations allowed) ----------------
__device__ float g_xp[NITEMS];       // x projections, [p][b][n] (segment-contiguous)
__device__ float g_yp[NITEMS];       // y projections
__device__ float g_delta[NITEMS];    // transported_proj - x_proj
__device__ float g_thn[PP * DD];     // normalized thetas, [p][d]
__device__ float g_thn_t[DD * PPAD]; // normalized thetas transposed, [d][p] (padded)

// ---------------- K1: normalize thetas ----------------
__global__ void __launch_bounds__(128) norm_kernel(const float* __restrict__ thetas) {
    int p = blockIdx.x;   // 0..127
    int d = threadIdx.x;  // 0..127
    __shared__ float red[4];
    float v = (p < PP) ? thetas[p * DD + d] : 0.f;
    float ss = v * v;
    #pragma unroll
    for (int o = 16; o; o >>= 1) ss += __shfl_xor_sync(0xFFFFFFFFu, ss, o);
    if ((d & 31) == 0) red[d >> 5] = ss;
    __syncthreads();
    float tot = red[0] + red[1] + red[2] + red[3];
    float w = 0.f;
    if (p < PP) {
        w = v / fmaxf(sqrtf(tot), 1e-12f);
        g_thn[p * DD + d] = w;
    }
    g_thn_t[d * PPAD + p] = w;  // zero for padded p
}

// ---------------- K2: projections (fp32 GEMM, 8x8 per thread) ----------------
// bn tile = 256, 512 threads (16 warps/SM for latency hiding), 256 blocks
// (1.73 waves), theta tile loaded once per block and reused for x and y.
#define BNT 256
#define XT_PITCH (BNT + 8)    // 264
#define PROJ_SMEM ((DD * PPAD + DD * XT_PITCH) * 4)   // 64KB + 135KB = 200.7KB

__global__ void __launch_bounds__(512, 1) proj_kernel(const float* __restrict__ x,
                                                      const float* __restrict__ y) {
    extern __shared__ float psm[];
    float* th_s = psm;                 // [d * 128 + p]
    float* xt_s = psm + DD * PPAD;     // [d * 264 + r]
    int tid = threadIdx.x;
    int bn0 = blockIdx.x * BNT;

    #pragma unroll
    for (int i = tid; i < DD * PPAD; i += 512) th_s[i] = g_thn_t[i];

    const float* srcs[2] = {x, y};
    float* dsts[2] = {g_xp, g_yp};
    int tx = tid & 31;   // bn lane: bn = bn0 + tx + 32*j, j<8
    int ty = tid >> 5;   // p group: p = ty*8 + pi (uniform per warp -> th_s broadcast)

    for (int a = 0; a < 2; a++) {
        const float* src = srcs[a];
        __syncthreads();  // protect xt_s reuse (also orders th_s on a==0)
        for (int e = tid; e < DD * BNT; e += 512) {
            int r = e >> 7, d = e & 127;   // d coalesced within each row
            xt_s[d * XT_PITCH + r] = src[(size_t)(bn0 + r) * DD + d];
        }
        __syncthreads();

        float acc[8][8];
        #pragma unroll
        for (int i = 0; i < 8; i++)
            #pragma unroll
            for (int j = 0; j < 8; j++) acc[i][j] = 0.f;

        #pragma unroll 4
        for (int d = 0; d < DD; d++) {
            float4 a0 = *(const float4*)&th_s[d * PPAD + ty * 8];
            float4 a1 = *(const float4*)&th_s[d * PPAD + ty * 8 + 4];
            float av[8] = {a0.x, a0.y, a0.z, a0.w, a1.x, a1.y, a1.z, a1.w};
            float bv[8];
            #pragma unroll
            for (int j = 0; j < 8; j++) bv[j] = xt_s[d * XT_PITCH + tx + 32 * j];
            #pragma unroll
            for (int pi = 0; pi < 8; pi++)
                #pragma unroll
                for (int j = 0; j < 8; j++) acc[pi][j] = fmaf(av[pi], bv[j], acc[pi][j]);
        }

        float* dst = dsts[a];
        #pragma unroll
        for (int pi = 0; pi < 8; pi++) {
            int p = ty * 8 + pi;
            if (p < PP) {
                #pragma unroll
                for (int j = 0; j < 8; j++)
                    dst[(size_t)p * BN + bn0 + tx + 32 * j] = acc[pi][j];
            }
        }
    }
}

// ---------------- K3: counting-rank transport, ONE atomic per element ----------------
// 16384 linear bins over [-6,6]; within-bin order arbitrary (ranks remain an
// exact permutation; value mismatch <= bin width 7.3e-4 -> output err ~6e-6).
// Histogram atomicAdd RETURN VALUE = within-bin arrival; stash (bin<<18)|arr;
// after exclusive scan, rank = hist[bin] + arrival -> scatter is atomic-free.
// 1024 threads (32 warps) to hide ATOMS return latency and halve scan rounds.
#define ST 1024
#define NBIN 16384
#define BINS_PER_WARP (NBIN / 32)          // 512
#define SCAN_ROUNDS (BINS_PER_WARP / 32)   // 16
// dynamic smem: hist 64KB + ys 64KB + saux 64KB = 192KB
#define SD_SMEM (NBIN * 4 + NN * 4 + NN * 4)

__device__ __forceinline__ int binof(float v) {
    // monotone: fp add/mul by positive const + truncation preserve order
    int b = (int)((v + 6.0f) * (float)(NBIN / 12.0));
    return min(max(b, 0), NBIN - 1);
}

__global__ void __launch_bounds__(ST, 1) sortdelta_kernel() {
    extern __shared__ char sdm[];
    int* hist = (int*)sdm;
    float* ys = (float*)(sdm + NBIN * 4);
    unsigned* saux = (unsigned*)(sdm + NBIN * 4 + NN * 4);
    __shared__ int wsum[32];

    int seg = blockIdx.x;
    size_t base = (size_t)seg * NN;
    int t = threadIdx.x, lane = t & 31, warp = t >> 5;

    #pragma unroll 1
    for (int phase = 0; phase < 2; phase++) {
        const float* src = phase == 0 ? (g_yp + base) : (g_xp + base);

        // ---- zero + histogram; record per-element (bin, arrival) ----
        for (int i = t; i < NBIN; i += ST) hist[i] = 0;
        __syncthreads();
        #pragma unroll 4
        for (int i = t; i < NN; i += ST) {
            int b = binof(src[i]);
            unsigned a = (unsigned)atomicAdd(&hist[b], 1);
            saux[i] = ((unsigned)b << 18) | a;   // bin:14b | arrival:18b
        }
        __syncthreads();

        // ---- exclusive scan of NBIN counts (warp-strided, conflict-free) ----
        {
            int wbase = warp * BINS_PER_WARP;
            int carry = 0;
            #pragma unroll 4
            for (int r = 0; r < SCAN_ROUNDS; r++) {
                int idx = wbase + r * 32 + lane;
                int c = hist[idx];
                int inc = c;
                #pragma unroll
                for (int o = 1; o < 32; o <<= 1) {
                    int n = __shfl_up_sync(0xFFFFFFFFu, inc, o);
                    if (lane >= o) inc += n;
                }
                hist[idx] = carry + inc - c;  // exclusive
                carry += __shfl_sync(0xFFFFFFFFu, inc, 31);
            }
            if (lane == 0) wsum[warp] = carry;
        }
        __syncthreads();
        if (warp == 0) {
            int w = wsum[lane];
            #pragma unroll
            for (int o = 1; o < 32; o <<= 1) {
                int n = __shfl_up_sync(0xFFFFFFFFu, w, o);
                if (lane >= o) w += n;
            }
            wsum[lane] = w;  // inclusive
        }
        __syncthreads();
        if (warp > 0) {
            int off = wsum[warp - 1];
            int wbase = warp * BINS_PER_WARP;
            #pragma unroll 4
            for (int r = 0; r < SCAN_ROUNDS; r++)
                hist[wbase + r * 32 + lane] += off;
        }
        __syncthreads();

        // ---- scatter, atomic-free: rank = bin base + arrival ----
        if (phase == 0) {
            #pragma unroll 4
            for (int i = t; i < NN; i += ST) {
                unsigned u = saux[i];
                int r = hist[u >> 18] + (int)(u & 0x3FFFFu);
                ys[r] = src[i];
            }
        } else {
            #pragma unroll 4
            for (int i = t; i < NN; i += ST) {
                unsigned u = saux[i];
                int r = hist[u >> 18] + (int)(u & 0x3FFFFu);
                g_delta[base + i] = ys[r] - src[i];
            }
        }
        __syncthreads();  // ys complete / hist+saux reuse
    }
}

// ---------------- K4: out = x + (Delta^T @ Thn)/P ----------------
#define OUT_SMEM (2 * PP * DD * 4)   // 102.4KB -> 2 CTAs/SM

__global__ void __launch_bounds__(256, 2) out_kernel(const float* __restrict__ x,
                                                     float* __restrict__ out) {
    extern __shared__ float osm[];
    float* dl_s = osm;             // [p][bn_local] 100x128
    float* th_s = osm + PP * DD;   // [p][d]        100x128
    int tid = threadIdx.x;
    int bn0 = blockIdx.x * 128;

    for (int e = tid; e < PP * DD; e += 256) {
        th_s[e] = g_thn[e];
        int p = e >> 7, j = e & 127;
        dl_s[e] = g_delta[(size_t)p * BN + bn0 + j];
    }
    __syncthreads();

    int tx = tid & 15;  // d lane: d = tx + 16*k
    int ty = tid >> 4;  // bn group: bn = bn0 + ty*8 + bi

    float acc[8][8];
    #pragma unroll
    for (int i = 0; i < 8; i++)
        #pragma unroll
        for (int j = 0; j < 8; j++) acc[i][j] = 0.f;

    #pragma unroll 4
    for (int p = 0; p < PP; p++) {
        float4 a0 = *(const float4*)&dl_s[p * DD + ty * 8];
        float4 a1 = *(const float4*)&dl_s[p * DD + ty * 8 + 4];
        float av[8] = {a0.x, a0.y, a0.z, a0.w, a1.x, a1.y, a1.z, a1.w};
        float bv[8];
        #pragma unroll
        for (int k = 0; k < 8; k++) bv[k] = th_s[p * DD + tx + 16 * k];
        #pragma unroll
        for (int bi = 0; bi < 8; bi++)
            #pragma unroll
            for (int k = 0; k < 8; k++) acc[bi][k] = fmaf(av[bi], bv[k], acc[bi][k]);
    }

    const float s = 1.0f / (float)PP;
    #pragma unroll
    for (int bi = 0; bi < 8; bi++) {
        size_t row = (size_t)(bn0 + ty * 8 + bi) * DD;
        #pragma unroll
        for (int k = 0; k < 8; k++) {
            size_t o = row + tx + 16 * k;
            out[o] = x[o] + s * acc[bi][k];
        }
    }
}

// ---------------- launch ----------------
extern "C" void kernel_launch(void* const* d_in, const int* in_sizes, int n_in,
                              void* d_out, int out_size) {
    const float* x = (const float*)d_in[0];
    const float* y = (const float*)d_in[1];
    const float* th = (const float*)d_in[2];
    float* out = (float*)d_out;
    (void)in_sizes; (void)n_in; (void)out_size;

    cudaFuncSetAttribute(proj_kernel,      cudaFuncAttributeMaxDynamicSharedMemorySize, PROJ_SMEM);
    cudaFuncSetAttribute(sortdelta_kernel, cudaFuncAttributeMaxDynamicSharedMemorySize, SD_SMEM);
    cudaFuncSetAttribute(out_kernel,       cudaFuncAttributeMaxDynamicSharedMemorySize, OUT_SMEM);

    norm_kernel<<<128, 128>>>(th);
    proj_kernel<<<BN / BNT, 512, PROJ_SMEM>>>(x, y);
    sortdelta_kernel<<<NSEG, ST, SD_SMEM>>>();
    out_kernel<<<512, 256, OUT_SMEM>>>(x, out);
}